// round 4
// baseline (speedup 1.0000x reference)
#include <cuda_runtime.h>
#include <cstdint>

// CTC forward, scaled linear-domain FP64 forward algorithm.
// One CTA per batch element; 256 threads; 4 lattice states per thread in
// REGISTERS. Neighbor exchange via shfl_up + per-warp smem halo.
// Power-of-2 global rescale every 64 steps; integer exponent accumulator Z.

#define T_DIM 2000
#define V_DIM 256
#define S_DIM 400
#define L_DIM 801
#define NT    256
#define KEXP  850
#define RMASK 63

__device__ float g_partial[64];

__device__ __forceinline__ float ex2f(float x) {
    float y; asm("ex2.approx.f32 %0, %1;" : "=f"(y) : "f"(x)); return y;
}
__device__ __forceinline__ float lg2f(float x) {
    float y; asm("lg2.approx.f32 %0, %1;" : "=f"(y) : "f"(x)); return y;
}

__global__ __launch_bounds__(NT, 1)
void ctc_kernel(const float* __restrict__ logp,
                const int*   __restrict__ targets,
                const int*   __restrict__ ilen,
                const int*   __restrict__ tlen)
{
    __shared__ double prow[2][V_DIM];     // probabilities (f64), double-buffered
    __shared__ double bnd[2][8][2];       // per-warp halo {A2, A3}, parity-buffered
    __shared__ int    wmax[8];
    __shared__ double Cslot;
    __shared__ double essum[2];

    const int b    = blockIdx.x;
    const int tid  = threadIdx.x;
    const int lane = tid & 31;
    const int w    = tid >> 5;
    const float* lpb = logp + (size_t)b * T_DIM * V_DIM;
    const int il  = ilen[b];
    const int tl  = tlen[b];
    const int end = 2 * tl;
    const int base = tid * 4;
    const float l2e = 1.4426950408889634f;

    // --- per-state labels / masks (states base .. base+3) ---
    int lbl1 = 1, lbl3 = 1;
    bool v0, v1, v2, v3, sk1 = false, sk3 = false;
    {
        const int s0 = base, s1 = base + 1, s2 = base + 2, s3 = base + 3;
        v0 = (s0 < L_DIM) && (s0 <= end);
        v1 = (s1 < L_DIM) && (s1 <= end);
        v2 = (s2 < L_DIM) && (s2 <= end);
        v3 = (s3 < L_DIM) && (s3 <= end);
        const int* tgt = targets + b * S_DIM;
        if (s1 < L_DIM) {
            lbl1 = tgt[2 * tid];
            if (s1 >= 3) sk1 = (lbl1 != tgt[2 * tid - 1]);
        }
        if (s3 < L_DIM) {
            lbl3 = tgt[2 * tid + 1];
            sk3 = (lbl3 != tgt[2 * tid]);
        }
    }

    // --- prob rows 0 and 1 ---
    prow[0][tid] = (double)ex2f(lpb[tid] * l2e);
    prow[1][tid] = (double)ex2f(lpb[V_DIM + tid] * l2e);
    if (tid == 0) Cslot = 1.0;
    __syncthreads();

    // --- t = 0 init: alpha0 = p0 * 2^K (states 0,1 live in thread 0) ---
    const double K2 = __longlong_as_double(((long long)(KEXP + 1023)) << 52);
    double A0 = 0.0, A1 = 0.0, A2 = 0.0, A3 = 0.0;
    if (tid == 0) {
        A0 = prow[0][1] * K2;
        A1 = prow[0][lbl1] * K2;
    }
    if (lane == 31) { bnd[0][w][0] = A2; bnd[0][w][1] = A3; }

    // --- logp prefetch queue, depth 3 (rows 2,3,4) ---
    float lp0 = 0.f, lp1 = 0.f, lp2 = 0.f;
    const float* lptr = lpb + 2 * V_DIM + tid;
    if (il > 2) lp0 = lptr[0];
    if (il > 3) lp1 = lptr[V_DIM];
    if (il > 4) lp2 = lptr[2 * V_DIM];
    lptr += 3 * V_DIM;
    __syncthreads();

    int Z = KEXP;   // meaningful in thread 0 only

    // --- main recursion ---
    for (int t = 1; t < il; ++t) {
        const double* pr  = prow[t & 1];
        double*       prw = prow[(t + 1) & 1];

        // neighbor states base-1 (n1), base-2 (n2)
        double n1 = __shfl_up_sync(0xffffffffu, A3, 1);
        double n2 = __shfl_up_sync(0xffffffffu, A2, 1);
        if (lane == 0) {
            if (w > 0) { n2 = bnd[(t + 1) & 1][w - 1][0]; n1 = bnd[(t + 1) & 1][w - 1][1]; }
            else       { n1 = 0.0; n2 = 0.0; }
        }

        // gather probabilities (blank prob shared by even states)
        double pB = pr[1];
        double p1 = pr[lbl1];
        double p3 = pr[lbl3];
        if ((t & RMASK) == 1) {
            double C = Cslot;
            pB *= C; p1 *= C; p3 *= C;
        }

        double z1 = sk1 ? n1 : 0.0;
        double z3 = sk3 ? A1 : 0.0;
        double t0 = (A0 + n1) * pB;
        double t1 = ((A1 + A0) + z1) * p1;
        double t2 = (A2 + A1) * pB;
        double t3 = ((A3 + A2) + z3) * p3;
        A0 = v0 ? t0 : 0.0;
        A1 = v1 ? t1 : 0.0;
        A2 = v2 ? t2 : 0.0;
        A3 = v3 ? t3 : 0.0;

        if (lane == 31) { bnd[t & 1][w][0] = A2; bnd[t & 1][w][1] = A3; }

        if ((t & RMASK) == 0) {   // measure block max (hi-bits; all alphas >= 0)
            int h = __double2hiint(A0);
            h = max(h, __double2hiint(A1));
            h = max(h, __double2hiint(A2));
            h = max(h, __double2hiint(A3));
            unsigned mm = __reduce_max_sync(0xffffffffu, (unsigned)h);
            if (lane == 0) wmax[w] = (int)mm;
        }

        // converter: prob row t+1 (other parity buffer)
        if (t + 1 < il) prw[tid] = (double)ex2f(lp0 * l2e);
        lp0 = lp1; lp1 = lp2;
        if (t + 4 < il) lp2 = *lptr;
        lptr += V_DIM;

        __syncthreads();

        if ((t & RMASK) == 0) {   // reducer: scale for step t+1
            if (w == 0) {
                unsigned v = (lane < 8) ? (unsigned)wmax[lane] : 0u;
                unsigned m = __reduce_max_sync(0xffffffffu, v);
                if (tid == 0) {
                    int e  = (int)(m >> 20) - 1023;
                    int sh = KEXP - e;
                    sh = max(-1000, min(1000, sh));
                    Cslot = __longlong_as_double(((long long)(sh + 1023)) << 52);
                    if (t + 1 < il) Z += sh;
                }
            }
            __syncthreads();
        }
    }

    // --- epilogue: collect states end, end-1 ---
    {
        const int s0 = base;
        if (s0     == end)     essum[0] = A0;
        if (s0     == end - 1) essum[1] = A0;
        if (s0 + 1 == end)     essum[0] = A1;
        if (s0 + 1 == end - 1) essum[1] = A1;
        if (s0 + 2 == end)     essum[0] = A2;
        if (s0 + 2 == end - 1) essum[1] = A2;
        if (s0 + 3 == end)     essum[0] = A3;
        if (s0 + 3 == end - 1) essum[1] = A3;
    }
    __syncthreads();

    if (tid == 0) {
        double ssum = essum[0] + essum[1];
        float loss;
        if (ssum <= 0.0) {
            loss = 0.0f;
        } else {
            long long bits = __double_as_longlong(ssum);
            int e2 = (int)((unsigned long long)bits >> 52) - 1023;
            double mant = __longlong_as_double((bits & 0x000FFFFFFFFFFFFFLL)
                                               | 0x3FF0000000000000LL);
            double ll = 0.6931471805599453 *
                        ((double)e2 + (double)lg2f((float)mant) - (double)Z);
            loss = (float)(-ll);
            if (!(loss < 1e29f)) loss = 0.0f;
        }
        g_partial[b] = loss / (float)tl;
    }
}

__global__ void reduce_kernel(float* out, int B)
{
    float v = 0.0f;
    for (int i = threadIdx.x; i < B; i += 32) v += g_partial[i];
    #pragma unroll
    for (int off = 16; off; off >>= 1)
        v += __shfl_xor_sync(0xffffffffu, v, off);
    if (threadIdx.x == 0) out[0] = v / (float)B;
}

extern "C" void kernel_launch(void* const* d_in, const int* in_sizes, int n_in,
                              void* d_out, int out_size)
{
    const float* logp    = (const float*)d_in[0];
    const int*   targets = (const int*)d_in[1];
    const int*   il      = (const int*)d_in[2];
    const int*   tl      = (const int*)d_in[3];
    const int B = in_sizes[2];

    ctc_kernel<<<B, NT>>>(logp, targets, il, tl);
    reduce_kernel<<<1, 32>>>((float*)d_out, B);
}